// round 8
// baseline (speedup 1.0000x reference)
#include <cuda_runtime.h>
#include <cuda_fp16.h>
#include <math.h>

// Inputs (metadata order): Xemb [8192,128] f32, scores f32 (unused),
// h_bias scalar f32, labels i32 (unused), pos_idx [P,2] i32, neg_idx [P,2] i32.
// Output: 2 floats {pos_loss, neg_loss}.

#define N_ROWS     8192
#define NUM_BLOCKS 592    // 148 SMs * 4
#define THREADS    256    // 8 warps/block

__device__ __half2 g_Xh[N_ROWS * 64];   // fp16-staged Xemb (2 MB)
__device__ float2 g_partials[NUM_BLOCKS];
__device__ unsigned int g_done_count = 0;

__global__ void convert_kernel(const float* __restrict__ X)
{
    const int t = blockIdx.x * blockDim.x + threadIdx.x;   // over 8192*32
    if (t < N_ROWS * 32) {
        float4 v = ((const float4*)X)[t];
        g_Xh[t * 2]     = __floats2half2_rn(v.x, v.y);
        g_Xh[t * 2 + 1] = __floats2half2_rn(v.z, v.w);
    }
}

// Accumulate (a-b)^2 for 8 halves in packed fp16.
__device__ __forceinline__ void acc8h(uint4 a, uint4 b, __half2& acc)
{
    const __half2* ah = (const __half2*)&a;
    const __half2* bh = (const __half2*)&b;
    #pragma unroll
    for (int j = 0; j < 4; j++) {
        __half2 d = __hsub2(ah[j], bh[j]);
        acc = __hfma2(d, d, acc);
    }
}

// Full-row exact distance^2 for one pair (8-lane group), fp16 math.
__device__ __forceinline__ float full_pair_s(const uint4* __restrict__ Xh,
                                             int2 idx, int sub, unsigned gmask)
{
    const uint4* ra = Xh + (size_t)idx.x * 16;
    const uint4* rb = Xh + (size_t)idx.y * 16;
    uint4 a0 = __ldg(ra + sub); uint4 a1 = __ldg(ra + sub + 8);
    uint4 b0 = __ldg(rb + sub); uint4 b1 = __ldg(rb + sub + 8);
    __half2 acc = __float2half2_rn(0.f);
    acc8h(a0, b0, acc); acc8h(a1, b1, acc);
    float s = __low2float(acc) + __high2float(acc);
    s += __shfl_xor_sync(gmask, s, 1);
    s += __shfl_xor_sync(gmask, s, 2);
    s += __shfl_xor_sync(gmask, s, 4);
    return s;
}

__global__ __launch_bounds__(THREADS, 4)
void pair_loss_fused_kernel(const float* __restrict__ h_bias,
                            const int2* __restrict__ pos_idx,
                            const int2* __restrict__ neg_idx,
                            int P,
                            float* __restrict__ out)
{
    const int lane  = threadIdx.x & 31;
    const int warp  = threadIdx.x >> 5;
    const int grp   = lane >> 3;       // 0..3: pair within the warp
    const int sub   = lane & 7;        // 0..7: lane within the pair group
    const unsigned gmask = 0xFFu << (grp * 8);
    const int gwarp = (blockIdx.x * blockDim.x + threadIdx.x) >> 5;
    const int G     = ((NUM_BLOCKS * THREADS) >> 5) * 4;   // total groups
    const long g0   = (long)gwarp * 4;
    const long ggrp = g0 + grp;

    const float bias   = log1pf(expf(*h_bias));  // softplus
    const float thresh = bias * bias + 2.0f;     // generous fp16 safety margin

    float pos_acc = 0.0f;
    float neg_acc = 0.0f;

    const uint4* Xh  = (const uint4*)g_Xh;
    const uint2* Xh2 = (const uint2*)g_Xh;       // row = 32 uint2

    // ---- positive pairs: full rows, 2 per group-iteration ----
    {
        const long nIter = (P > g0) ? ((P - 1 - g0) / G + 1) : 0;
        long t = ggrp;
        for (long k = 0; k < nIter; k += 2, t += 2L * G) {
            const long t2 = t + G;
            const int2 i1 = (t  < P) ? __ldg(&pos_idx[t])  : make_int2(0, 0);
            const int2 i2 = (t2 < P && k + 1 < nIter) ? __ldg(&pos_idx[t2]) : make_int2(0, 0);

            const uint4* ra1 = Xh + (size_t)i1.x * 16;
            const uint4* rb1 = Xh + (size_t)i1.y * 16;
            const uint4* ra2 = Xh + (size_t)i2.x * 16;
            const uint4* rb2 = Xh + (size_t)i2.y * 16;
            uint4 a10 = __ldg(ra1 + sub); uint4 a11 = __ldg(ra1 + sub + 8);
            uint4 b10 = __ldg(rb1 + sub); uint4 b11 = __ldg(rb1 + sub + 8);
            uint4 a20 = __ldg(ra2 + sub); uint4 a21 = __ldg(ra2 + sub + 8);
            uint4 b20 = __ldg(rb2 + sub); uint4 b21 = __ldg(rb2 + sub + 8);

            __half2 acc1 = __float2half2_rn(0.f);
            __half2 acc2 = __float2half2_rn(0.f);
            acc8h(a10, b10, acc1); acc8h(a11, b11, acc1);
            acc8h(a20, b20, acc2); acc8h(a21, b21, acc2);
            pos_acc += __low2float(acc1) + __high2float(acc1);
            pos_acc += __low2float(acc2) + __high2float(acc2);
        }
    }

    // ---- negative pairs: 64B/row probe + exact early-exit, 2 per iter ----
    {
        const long nIter = (P > g0) ? ((P - 1 - g0) / G + 1) : 0;
        long t = ggrp;
        for (long k = 0; k < nIter; k += 2, t += 2L * G) {
            const long t2 = t + G;
            const bool v1 = (t  < P);
            const bool v2 = (t2 < P) && (k + 1 < nIter);
            const int2 i1 = v1 ? __ldg(&neg_idx[t])  : make_int2(0, 0);
            const int2 i2 = v2 ? __ldg(&neg_idx[t2]) : make_int2(0, 0);

            // probe: lane loads uint2 (4 halves) from the first 64B of each row
            uint2 a1 = __ldg(Xh2 + (size_t)i1.x * 32 + sub);
            uint2 b1 = __ldg(Xh2 + (size_t)i1.y * 32 + sub);
            uint2 a2 = __ldg(Xh2 + (size_t)i2.x * 32 + sub);
            uint2 b2 = __ldg(Xh2 + (size_t)i2.y * 32 + sub);

            const __half2* a1h = (const __half2*)&a1;
            const __half2* b1h = (const __half2*)&b1;
            const __half2* a2h = (const __half2*)&a2;
            const __half2* b2h = (const __half2*)&b2;
            __half2 p1 = __float2half2_rn(0.f);
            __half2 p2 = __float2half2_rn(0.f);
            #pragma unroll
            for (int j = 0; j < 2; j++) {
                __half2 d1 = __hsub2(a1h[j], b1h[j]);
                __half2 d2 = __hsub2(a2h[j], b2h[j]);
                p1 = __hfma2(d1, d1, p1);
                p2 = __hfma2(d2, d2, p2);
            }
            float s1 = __low2float(p1) + __high2float(p1);
            float s2 = __low2float(p2) + __high2float(p2);
            s1 += __shfl_xor_sync(0xFFFFFFFFu, s1, 1);
            s2 += __shfl_xor_sync(0xFFFFFFFFu, s2, 1);
            s1 += __shfl_xor_sync(0xFFFFFFFFu, s1, 2);
            s2 += __shfl_xor_sync(0xFFFFFFFFu, s2, 2);
            s1 += __shfl_xor_sync(0xFFFFFFFFu, s1, 4);
            s2 += __shfl_xor_sync(0xFFFFFFFFu, s2, 4);
            if (!v1) s1 = 1e30f;   // invalid -> force fast path, contributes 0
            if (!v2) s2 = 1e30f;

            // If partial > thresh, full distance > bias -> relu term exactly 0.
            // Slow path (essentially never taken): exact full-row recompute.
            if (s1 <= thresh) {
                float sf = full_pair_s(Xh, i1, sub, gmask);
                const float dd = sqrtf(sf);
                const float r  = fmaxf(bias - dd, 0.0f);
                neg_acc += (sub == 0) ? r * r : 0.0f;
            }
            if (s2 <= thresh) {
                float sf = full_pair_s(Xh, i2, sub, gmask);
                const float dd = sqrtf(sf);
                const float r  = fmaxf(bias - dd, 0.0f);
                neg_acc += (sub == 0) ? r * r : 0.0f;
            }
        }
    }

    // ---- block reduce ----
    __shared__ float s_pos[THREADS / 32];
    __shared__ float s_neg[THREADS / 32];
    float p = pos_acc, n = neg_acc;
    #pragma unroll
    for (int o = 16; o > 0; o >>= 1) {
        p += __shfl_xor_sync(0xFFFFFFFFu, p, o);
        n += __shfl_xor_sync(0xFFFFFFFFu, n, o);
    }
    if (lane == 0) { s_pos[warp] = p; s_neg[warp] = n; }
    __syncthreads();

    __shared__ bool s_is_last;
    if (warp == 0) {
        float pp = (lane < THREADS / 32) ? s_pos[lane] : 0.0f;
        float nn = (lane < THREADS / 32) ? s_neg[lane] : 0.0f;
        #pragma unroll
        for (int o = 4; o > 0; o >>= 1) {
            pp += __shfl_xor_sync(0xFFFFFFFFu, pp, o);
            nn += __shfl_xor_sync(0xFFFFFFFFu, nn, o);
        }
        if (lane == 0) {
            g_partials[blockIdx.x] = make_float2(pp, nn);
            __threadfence();
            unsigned int prev = atomicAdd(&g_done_count, 1u);
            s_is_last = (prev == (unsigned int)(gridDim.x - 1));
        }
    }
    __syncthreads();

    // ---- last block: final deterministic reduction in double ----
    if (s_is_last) {
        double ps = 0.0, ns = 0.0;
        for (int i = threadIdx.x; i < NUM_BLOCKS; i += THREADS) {
            float2 v = g_partials[i];
            ps += (double)v.x;
            ns += (double)v.y;
        }
        #pragma unroll
        for (int o = 16; o > 0; o >>= 1) {
            ps += __shfl_xor_sync(0xFFFFFFFFu, ps, o);
            ns += __shfl_xor_sync(0xFFFFFFFFu, ns, o);
        }
        __shared__ double sp[THREADS / 32], sn[THREADS / 32];
        if (lane == 0) { sp[warp] = ps; sn[warp] = ns; }
        __syncthreads();
        if (threadIdx.x == 0) {
            double tp = 0.0, tn = 0.0;
            for (int w = 0; w < THREADS / 32; w++) { tp += sp[w]; tn += sn[w]; }
            out[0] = (float)(0.5 * tp / (double)P);
            out[1] = (float)(0.5 * tn / (double)P);
            g_done_count = 0;   // reset for next graph replay
        }
    }
}

extern "C" void kernel_launch(void* const* d_in, const int* in_sizes, int n_in,
                              void* d_out, int out_size)
{
    const float* X      = (const float*)d_in[0];
    const float* h_bias = (const float*)d_in[2];
    const int2*  pos    = (const int2*)d_in[4];
    const int2*  neg    = (const int2*)d_in[5];
    const int P = in_sizes[4] / 2;

    convert_kernel<<<(N_ROWS * 32 + 255) / 256, 256>>>(X);
    pair_loss_fused_kernel<<<NUM_BLOCKS, THREADS>>>(h_bias, pos, neg, P, (float*)d_out);
}

// round 9
// speedup vs baseline: 1.5000x; 1.5000x over previous
#include <cuda_runtime.h>
#include <cuda_fp16.h>
#include <math.h>

// Inputs (metadata order): Xemb [8192,128] f32, scores f32 (unused),
// h_bias scalar f32, labels i32 (unused), pos_idx [P,2] i32, neg_idx [P,2] i32.
// Output: 2 floats {pos_loss, neg_loss}.

#define N_ROWS     8192
#define NUM_BLOCKS 592    // 148 SMs * 4
#define THREADS    256    // 8 warps/block

__device__ __half2 g_Xh[N_ROWS * 64];   // fp16-staged Xemb (2 MB)
__device__ float2 g_partials[NUM_BLOCKS];
__device__ unsigned int g_done_count = 0;

__global__ void convert_kernel(const float* __restrict__ X)
{
    const int t = blockIdx.x * blockDim.x + threadIdx.x;   // over 8192*32
    if (t < N_ROWS * 32) {
        float4 v = ((const float4*)X)[t];
        g_Xh[t * 2]     = __floats2half2_rn(v.x, v.y);
        g_Xh[t * 2 + 1] = __floats2half2_rn(v.z, v.w);
    }
}

// Accumulate (a-b)^2 for 8 halves in packed fp16.
__device__ __forceinline__ void acc8h(uint4 a, uint4 b, __half2& acc)
{
    const __half2* ah = (const __half2*)&a;
    const __half2* bh = (const __half2*)&b;
    #pragma unroll
    for (int j = 0; j < 4; j++) {
        __half2 d = __hsub2(ah[j], bh[j]);
        acc = __hfma2(d, d, acc);
    }
}

// Full-row distance^2 for one pair, computed by a 4-lane group.
__device__ __forceinline__ float full_pair_s4(const uint4* __restrict__ Xh,
                                              int2 idx, int sub4, unsigned gmask)
{
    const uint4* ra = Xh + (size_t)idx.x * 16;
    const uint4* rb = Xh + (size_t)idx.y * 16;
    uint4 a0 = __ldg(ra + sub4);      uint4 a1 = __ldg(ra + sub4 + 4);
    uint4 a2 = __ldg(ra + sub4 + 8);  uint4 a3 = __ldg(ra + sub4 + 12);
    uint4 b0 = __ldg(rb + sub4);      uint4 b1 = __ldg(rb + sub4 + 4);
    uint4 b2 = __ldg(rb + sub4 + 8);  uint4 b3 = __ldg(rb + sub4 + 12);
    __half2 acc = __float2half2_rn(0.f);
    acc8h(a0, b0, acc); acc8h(a1, b1, acc);
    acc8h(a2, b2, acc); acc8h(a3, b3, acc);
    float s = __low2float(acc) + __high2float(acc);
    s += __shfl_xor_sync(gmask, s, 1);
    s += __shfl_xor_sync(gmask, s, 2);
    return s;
}

__global__ __launch_bounds__(THREADS, 4)
void pair_loss_fused_kernel(const float* __restrict__ h_bias,
                            const int2* __restrict__ pos_idx,
                            const int2* __restrict__ neg_idx,
                            int P,
                            float* __restrict__ out)
{
    const int lane  = threadIdx.x & 31;
    const int warp  = threadIdx.x >> 5;
    const int gwarp = (blockIdx.x * blockDim.x + threadIdx.x) >> 5;
    const int nWarps = (NUM_BLOCKS * THREADS) >> 5;

    const float bias   = log1pf(expf(*h_bias));  // softplus
    const float thresh = bias * bias + 2.0f;     // generous fp16 safety margin

    float pos_acc = 0.0f;
    float neg_acc = 0.0f;

    const uint4* Xh = (const uint4*)g_Xh;        // row = 16 uint4 (256B)

    // ---- positive pairs: 8 lanes/pair, full rows, 2 per group-iteration ----
    {
        const int grp = lane >> 3;       // 0..3
        const int sub = lane & 7;        // 0..7
        const int G   = nWarps * 4;
        const long g0 = (long)gwarp * 4;
        const long nIter = (P > g0) ? ((P - 1 - g0) / G + 1) : 0;
        long t = g0 + grp;
        for (long k = 0; k < nIter; k += 2, t += 2L * G) {
            const long t2 = t + G;
            const int2 i1 = (t  < P) ? __ldg(&pos_idx[t])  : make_int2(0, 0);
            const int2 i2 = (t2 < P && k + 1 < nIter) ? __ldg(&pos_idx[t2]) : make_int2(0, 0);

            const uint4* ra1 = Xh + (size_t)i1.x * 16;
            const uint4* rb1 = Xh + (size_t)i1.y * 16;
            const uint4* ra2 = Xh + (size_t)i2.x * 16;
            const uint4* rb2 = Xh + (size_t)i2.y * 16;
            uint4 a10 = __ldg(ra1 + sub); uint4 a11 = __ldg(ra1 + sub + 8);
            uint4 b10 = __ldg(rb1 + sub); uint4 b11 = __ldg(rb1 + sub + 8);
            uint4 a20 = __ldg(ra2 + sub); uint4 a21 = __ldg(ra2 + sub + 8);
            uint4 b20 = __ldg(rb2 + sub); uint4 b21 = __ldg(rb2 + sub + 8);

            __half2 acc1 = __float2half2_rn(0.f);
            __half2 acc2 = __float2half2_rn(0.f);
            acc8h(a10, b10, acc1); acc8h(a11, b11, acc1);
            acc8h(a20, b20, acc2); acc8h(a21, b21, acc2);
            pos_acc += __low2float(acc1) + __high2float(acc1);
            pos_acc += __low2float(acc2) + __high2float(acc2);
        }
    }

    // ---- negative pairs: 4 lanes/pair, 64B-probe early-exit, 2 per iter ----
    {
        const int grp4 = lane >> 2;      // 0..7
        const int sub4 = lane & 3;       // 0..3
        const unsigned gmask = 0xFu << (grp4 * 4);
        const int G8  = nWarps * 8;
        const long h0 = (long)gwarp * 8;
        const long nIter = (P > h0) ? ((P - 1 - h0) / G8 + 1) : 0;
        long t = h0 + grp4;
        for (long k = 0; k < nIter; k += 2, t += 2L * G8) {
            const long t2 = t + G8;
            const bool v1 = (t  < P);
            const bool v2 = (t2 < P) && (k + 1 < nIter);
            const int2 i1 = v1 ? __ldg(&neg_idx[t])  : make_int2(0, 0);
            const int2 i2 = v2 ? __ldg(&neg_idx[t2]) : make_int2(0, 0);

            // probe: first 64B of each row, full-width LDG.128 per lane
            uint4 a1 = __ldg(Xh + (size_t)i1.x * 16 + sub4);
            uint4 b1 = __ldg(Xh + (size_t)i1.y * 16 + sub4);
            uint4 a2 = __ldg(Xh + (size_t)i2.x * 16 + sub4);
            uint4 b2 = __ldg(Xh + (size_t)i2.y * 16 + sub4);

            __half2 p1 = __float2half2_rn(0.f);
            __half2 p2 = __float2half2_rn(0.f);
            acc8h(a1, b1, p1);
            acc8h(a2, b2, p2);
            float s1 = __low2float(p1) + __high2float(p1);
            float s2 = __low2float(p2) + __high2float(p2);
            s1 += __shfl_xor_sync(0xFFFFFFFFu, s1, 1);
            s2 += __shfl_xor_sync(0xFFFFFFFFu, s2, 1);
            s1 += __shfl_xor_sync(0xFFFFFFFFu, s1, 2);
            s2 += __shfl_xor_sync(0xFFFFFFFFu, s2, 2);
            if (!v1) s1 = 1e30f;   // invalid -> fast path, contributes 0
            if (!v2) s2 = 1e30f;

            // partial > thresh  =>  full distance > bias  =>  relu term == 0.
            if (s1 <= thresh) {
                float sf = full_pair_s4(Xh, i1, sub4, gmask);
                const float dd = sqrtf(sf);
                const float r  = fmaxf(bias - dd, 0.0f);
                neg_acc += (sub4 == 0) ? r * r : 0.0f;
            }
            if (s2 <= thresh) {
                float sf = full_pair_s4(Xh, i2, sub4, gmask);
                const float dd = sqrtf(sf);
                const float r  = fmaxf(bias - dd, 0.0f);
                neg_acc += (sub4 == 0) ? r * r : 0.0f;
            }
        }
    }

    // ---- block reduce ----
    __shared__ float s_pos[THREADS / 32];
    __shared__ float s_neg[THREADS / 32];
    float p = pos_acc, n = neg_acc;
    #pragma unroll
    for (int o = 16; o > 0; o >>= 1) {
        p += __shfl_xor_sync(0xFFFFFFFFu, p, o);
        n += __shfl_xor_sync(0xFFFFFFFFu, n, o);
    }
    if (lane == 0) { s_pos[warp] = p; s_neg[warp] = n; }
    __syncthreads();

    __shared__ bool s_is_last;
    if (warp == 0) {
        float pp = (lane < THREADS / 32) ? s_pos[lane] : 0.0f;
        float nn = (lane < THREADS / 32) ? s_neg[lane] : 0.0f;
        #pragma unroll
        for (int o = 4; o > 0; o >>= 1) {
            pp += __shfl_xor_sync(0xFFFFFFFFu, pp, o);
            nn += __shfl_xor_sync(0xFFFFFFFFu, nn, o);
        }
        if (lane == 0) {
            g_partials[blockIdx.x] = make_float2(pp, nn);
            __threadfence();
            unsigned int prev = atomicAdd(&g_done_count, 1u);
            s_is_last = (prev == (unsigned int)(gridDim.x - 1));
        }
    }
    __syncthreads();

    // ---- last block: final deterministic reduction in double ----
    if (s_is_last) {
        double ps = 0.0, ns = 0.0;
        for (int i = threadIdx.x; i < NUM_BLOCKS; i += THREADS) {
            float2 v = g_partials[i];
            ps += (double)v.x;
            ns += (double)v.y;
        }
        #pragma unroll
        for (int o = 16; o > 0; o >>= 1) {
            ps += __shfl_xor_sync(0xFFFFFFFFu, ps, o);
            ns += __shfl_xor_sync(0xFFFFFFFFu, ns, o);
        }
        __shared__ double sp[THREADS / 32], sn[THREADS / 32];
        if (lane == 0) { sp[warp] = ps; sn[warp] = ns; }
        __syncthreads();
        if (threadIdx.x == 0) {
            double tp = 0.0, tn = 0.0;
            for (int w = 0; w < THREADS / 32; w++) { tp += sp[w]; tn += sn[w]; }
            out[0] = (float)(0.5 * tp / (double)P);
            out[1] = (float)(0.5 * tn / (double)P);
            g_done_count = 0;   // reset for next graph replay
        }
    }
}

extern "C" void kernel_launch(void* const* d_in, const int* in_sizes, int n_in,
                              void* d_out, int out_size)
{
    const float* X      = (const float*)d_in[0];
    const float* h_bias = (const float*)d_in[2];
    const int2*  pos    = (const int2*)d_in[4];
    const int2*  neg    = (const int2*)d_in[5];
    const int P = in_sizes[4] / 2;

    convert_kernel<<<(N_ROWS * 32 + 255) / 256, 256>>>(X);
    pair_loss_fused_kernel<<<NUM_BLOCKS, THREADS>>>(h_bias, pos, neg, P, (float*)d_out);
}